// round 3
// baseline (speedup 1.0000x reference)
#include <cuda_runtime.h>

// PoseNoiseTransform single-pass decoupled-lookback quaternion scan.
//   q:     [TS, NS, 4] f32 unit quaternions (w,x,y,z)
//   noise: [TS-1, NS, 4] f32 uniform [0,1)
//   out:   [TS, NS, 4] f32
//
// out[0]   = q[0]
// q_dot[t] = (q[t+1] * conj(q[t])) * normalize((noise[t]-0.5)*[1,.05,.05,.05])
// out[i+1] = q_dot[i] * ... * q_dot[0] * q[0]
//
// Grid = (chunks x column-blocks), dynamic ticket ordering. Each block:
// walk1 (chunk aggregate) -> publish -> lookback -> walk2 (apply carry, write).
// Walk2 re-reads its chunk of q/noise, hot in L2 from walk1.

#define BLK 256
#define NCH 64          // chunks along time
#define NS_MAX 8192
#define CB_MAX 32       // max column-blocks (NS_MAX / BLK)

// Scratch (device globals; no allocation allowed anywhere).
__device__ float4 g_agg[NCH * NS_MAX];   // per-chunk aggregate, per column
__device__ float4 g_inc[NCH * NS_MAX];   // per-chunk inclusive prefix, per column
__device__ int    g_flag[CB_MAX * NCH];  // 0=none, 1=aggregate ready, 2=inclusive ready
__device__ unsigned int g_vid;           // dynamic virtual block id counter

// Quaternion in float4: .x=w .y=x .z=y .w=z ; returns a*b (Hamilton)
__device__ __forceinline__ float4 qmul(float4 a, float4 b) {
    float aw = a.x, ax = a.y, ay = a.z, az = a.w;
    float bw = b.x, bx = b.y, by = b.z, bz = b.w;
    return make_float4(
        aw * bw - ax * bx - ay * by - az * bz,
        aw * bx + ax * bw + ay * bz - az * by,
        aw * by - ax * bz + ay * bw + az * bx,
        aw * bz + ax * by - ay * bx + az * bw);
}

__device__ __forceinline__ float4 qdot_step(float4 qnext, float4 qprev, float4 nz) {
    // rel = qnext * conj(qprev), conj signs folded
    float aw = qnext.x, ax = qnext.y, ay = qnext.z, az = qnext.w;
    float bw = qprev.x, bx = -qprev.y, by = -qprev.z, bz = -qprev.w;
    float4 rel = make_float4(
        aw * bw - ax * bx - ay * by - az * bz,
        aw * bx + ax * bw + ay * bz - az * by,
        aw * by - ax * bz + ay * bw + az * bx,
        aw * bz + ax * by - ay * bx + az * bw);

    // q_samp = normalize((nz - 0.5) * [1, .05, .05, .05])
    float sw = nz.x - 0.5f;
    float sx = (nz.y - 0.5f) * 0.05f;
    float sy = (nz.z - 0.5f) * 0.05f;
    float sz = (nz.w - 0.5f) * 0.05f;
    float d = sw * sw + sx * sx + sy * sy + sz * sz;
    float r = rsqrtf(d);
    r = r * (1.5f - 0.5f * d * r * r);   // Newton step -> full fp32 accuracy
    float4 samp = make_float4(sw * r, sx * r, sy * r, sz * r);

    return qmul(rel, samp);
}

__global__ void init_kernel() {
    int i = blockIdx.x * blockDim.x + threadIdx.x;
    if (i < CB_MAX * NCH) g_flag[i] = 0;
    if (i == 0) g_vid = 0u;
}

__global__ void __launch_bounds__(BLK) scan_kernel(
    const float4* __restrict__ q, const float4* __restrict__ noise,
    float4* __restrict__ out, int NS, int T, int L, int CB)
{
    __shared__ unsigned int s_vid;
    __shared__ int s_flag;

    // Dynamic block id: scheduling order == chunk order -> lookback can't deadlock.
    if (threadIdx.x == 0) s_vid = atomicAdd(&g_vid, 1u);
    __syncthreads();
    unsigned int vid = s_vid;
    int c  = (int)(vid / (unsigned)CB);
    int cb = (int)(vid % (unsigned)CB);
    int n  = cb * BLK + threadIdx.x;
    bool active = (n < NS);

    int t0 = c * L;
    int t1 = min(T, t0 + L);

    // ---- Walk 1: chunk aggregate A = qdot[t1-1] * ... * qdot[t0] ----
    float4 A = make_float4(1.f, 0.f, 0.f, 0.f);
    if (active && t0 < T) {
        float4 qprev = q[(size_t)t0 * NS + n];
        #pragma unroll 4
        for (int t = t0; t < t1; ++t) {
            float4 qn = q[(size_t)(t + 1) * NS + n];
            float4 nz = noise[(size_t)t * NS + n];
            A = qmul(qdot_step(qn, qprev, nz), A);
            qprev = qn;
        }
    }

    // ---- Publish aggregate + lookback ----
    float4 S = make_float4(1.f, 0.f, 0.f, 0.f);  // exclusive prefix P_{c-1}
    if (c > 0) {
        if (active) g_agg[c * NS + n] = A;
        __threadfence();
        __syncthreads();
        if (threadIdx.x == 0) atomicExch(&g_flag[cb * NCH + c], 1);

        int p = c - 1;
        while (p >= 0) {
            if (threadIdx.x == 0) {
                int s;
                int backoff = 20;
                while ((s = atomicAdd(&g_flag[cb * NCH + p], 0)) == 0) {
                    __nanosleep(backoff);
                    if (backoff < 320) backoff += backoff;
                }
                s_flag = s;
            }
            __syncthreads();
            int s = s_flag;
            __syncthreads();
            __threadfence();
            if (s >= 2) {
                if (active) S = qmul(S, g_inc[p * NS + n]);
                break;
            } else {
                if (active) S = qmul(S, g_agg[p * NS + n]);
                --p;
            }
        }
    }

    // ---- Publish inclusive P_c = A * P_{c-1} ----
    float4 P = qmul(A, S);
    if (active) g_inc[c * NS + n] = P;
    __threadfence();
    __syncthreads();
    if (threadIdx.x == 0) atomicExch(&g_flag[cb * NCH + c], 2);

    if (!active || t0 >= T) return;

    // ---- Walk 2: apply carry, write outputs (chunk data hot in L2) ----
    float4 q0 = q[n];
    if (c == 0) out[n] = q0;                 // out[0] = q[0]
    float4 acc = qmul(S, q0);                // carry = P_{c-1} * q[0]
    float4 qprev = q[(size_t)t0 * NS + n];
    #pragma unroll 4
    for (int t = t0; t < t1; ++t) {
        float4 qn = q[(size_t)(t + 1) * NS + n];
        float4 nz = noise[(size_t)t * NS + n];
        acc = qmul(qdot_step(qn, qprev, nz), acc);
        out[(size_t)(t + 1) * NS + n] = acc;
        qprev = qn;
    }
}

extern "C" void kernel_launch(void* const* d_in, const int* in_sizes, int n_in,
                              void* d_out, int out_size)
{
    const float4* q     = (const float4*)d_in[0];
    const float4* noise = (const float4*)d_in[1];
    float4* out         = (float4*)d_out;

    int quats0 = in_sizes[0] / 4;          // TS*NS
    int quats1 = in_sizes[1] / 4;          // (TS-1)*NS
    int NS = quats0 - quats1;
    int TS = quats0 / NS;
    int T  = TS - 1;
    int L  = (T + NCH - 1) / NCH;          // chunk length
    int nch = (T + L - 1) / L;             // actual chunk count (<= NCH)
    int CB  = (NS + BLK - 1) / BLK;        // column-blocks

    init_kernel<<<8, 256>>>();
    scan_kernel<<<nch * CB, BLK>>>(q, noise, out, NS, T, L, CB);
}

// round 6
// speedup vs baseline: 1.2450x; 1.2450x over previous
#include <cuda_runtime.h>

// PoseNoiseTransform single-pass decoupled-lookback quaternion scan,
// with q_dot staged in SMEM (inputs read from DRAM exactly once).
//   q:     [TS, NS, 4] f32 unit quaternions (w,x,y,z)
//   noise: [TS-1, NS, 4] f32 uniform [0,1)
//   out:   [TS, NS, 4] f32
//
// out[0]   = q[0]
// q_dot[t] = (q[t+1] * conj(q[t])) * normalize((noise[t]-0.5)*[1,.05,.05,.05])
// out[i+1] = q_dot[i] * ... * q_dot[0] * q[0]
//
// Each block (chunk c, column-block cb):
//   walk1: compute q_dot for its CHUNK timesteps -> SMEM, accumulate aggregate
//   publish aggregate -> decoupled lookback -> exclusive carry S
//   walk2: replay q_dot from SMEM, write outputs (no global re-read)

#define BLK 256
#define CHUNK 11          // timesteps per block; SMEM = 256*11*16 = 45056 B (+8 B misc < 48 KB)
#define NCH_MAX 192
#define NS_MAX 8192
#define CB_MAX 32

// Scratch (device globals; no allocation allowed anywhere).
__device__ float4 g_agg[NCH_MAX * NS_MAX];
__device__ float4 g_inc[NCH_MAX * NS_MAX];
__device__ int    g_flag[CB_MAX * NCH_MAX];  // 0=none 1=agg 2=inclusive
__device__ unsigned int g_vid;

// Quaternion in float4: .x=w .y=x .z=y .w=z ; returns a*b (Hamilton)
__device__ __forceinline__ float4 qmul(float4 a, float4 b) {
    float aw = a.x, ax = a.y, ay = a.z, az = a.w;
    float bw = b.x, bx = b.y, by = b.z, bz = b.w;
    return make_float4(
        aw * bw - ax * bx - ay * by - az * bz,
        aw * bx + ax * bw + ay * bz - az * by,
        aw * by - ax * bz + ay * bw + az * bx,
        aw * bz + ax * by - ay * bx + az * bw);
}

__device__ __forceinline__ float4 qdot_step(float4 qnext, float4 qprev, float4 nz) {
    // rel = qnext * conj(qprev), conj signs folded
    float aw = qnext.x, ax = qnext.y, ay = qnext.z, az = qnext.w;
    float bw = qprev.x, bx = -qprev.y, by = -qprev.z, bz = -qprev.w;
    float4 rel = make_float4(
        aw * bw - ax * bx - ay * by - az * bz,
        aw * bx + ax * bw + ay * bz - az * by,
        aw * by - ax * bz + ay * bw + az * bx,
        aw * bz + ax * by - ay * bx + az * bw);

    // q_samp = normalize((nz - 0.5) * [1, .05, .05, .05])
    float sw = nz.x - 0.5f;
    float sx = (nz.y - 0.5f) * 0.05f;
    float sy = (nz.z - 0.5f) * 0.05f;
    float sz = (nz.w - 0.5f) * 0.05f;
    float d = sw * sw + sx * sx + sy * sy + sz * sz;
    float r = rsqrtf(d);
    r = r * (1.5f - 0.5f * d * r * r);   // Newton step -> full fp32 accuracy
    float4 samp = make_float4(sw * r, sx * r, sy * r, sz * r);

    return qmul(rel, samp);
}

__global__ void init_kernel() {
    int i = blockIdx.x * blockDim.x + threadIdx.x;
    if (i < CB_MAX * NCH_MAX) g_flag[i] = 0;
    if (i == 0) g_vid = 0u;
}

__global__ void __launch_bounds__(BLK) scan_kernel(
    const float4* __restrict__ q, const float4* __restrict__ noise,
    float4* __restrict__ out, int NS, int T, int CB)
{
    __shared__ float4 sdot[CHUNK][BLK];   // 44 KB: staged q_dot for this chunk
    __shared__ unsigned int s_vid;
    __shared__ int s_flag;

    // Dynamic block id: scheduling order == chunk order -> lookback safe.
    if (threadIdx.x == 0) s_vid = atomicAdd(&g_vid, 1u);
    __syncthreads();
    unsigned int vid = s_vid;
    int c  = (int)(vid / (unsigned)CB);
    int cb = (int)(vid % (unsigned)CB);
    int n  = cb * BLK + threadIdx.x;
    bool active = (n < NS);

    int t0 = c * CHUNK;
    int t1 = min(T, t0 + CHUNK);
    int len = t1 - t0;                    // 1..CHUNK

    // ---- Walk 1: compute q_dot -> SMEM, accumulate aggregate A ----
    float4 A = make_float4(1.f, 0.f, 0.f, 0.f);
    if (active) {
        float4 qprev = q[(size_t)t0 * NS + n];
        #pragma unroll
        for (int i = 0; i < CHUNK; ++i) {
            if (i < len) {
                int t = t0 + i;
                float4 qn = q[(size_t)(t + 1) * NS + n];
                float4 nz = noise[(size_t)t * NS + n];
                float4 qd = qdot_step(qn, qprev, nz);
                sdot[i][threadIdx.x] = qd;
                A = qmul(qd, A);
                qprev = qn;
            }
        }
    }

    // ---- Publish aggregate + lookback ----
    float4 S = make_float4(1.f, 0.f, 0.f, 0.f);  // exclusive prefix P_{c-1}
    if (c > 0) {
        if (active) g_agg[c * NS + n] = A;
        __threadfence();
        __syncthreads();
        if (threadIdx.x == 0) atomicExch(&g_flag[cb * NCH_MAX + c], 1);

        int p = c - 1;
        while (p >= 0) {
            if (threadIdx.x == 0) {
                int s;
                int backoff = 20;
                while ((s = atomicAdd(&g_flag[cb * NCH_MAX + p], 0)) == 0) {
                    __nanosleep(backoff);
                    if (backoff < 320) backoff += backoff;
                }
                s_flag = s;
            }
            __syncthreads();
            int s = s_flag;
            __syncthreads();
            __threadfence();
            if (s >= 2) {
                if (active) S = qmul(S, g_inc[p * NS + n]);
                break;
            } else {
                if (active) S = qmul(S, g_agg[p * NS + n]);
                --p;
            }
        }
    }

    // ---- Publish inclusive P_c = A * P_{c-1} ----
    float4 P = qmul(A, S);
    if (active) g_inc[c * NS + n] = P;
    __threadfence();
    __syncthreads();
    if (threadIdx.x == 0) atomicExch(&g_flag[cb * NCH_MAX + c], 2);

    if (!active) return;

    // ---- Walk 2: replay q_dot from SMEM, write outputs ----
    float4 q0 = q[n];
    if (c == 0) out[n] = q0;              // out[0] = q[0]
    float4 acc = qmul(S, q0);             // carry = P_{c-1} * q[0]
    #pragma unroll
    for (int i = 0; i < CHUNK; ++i) {
        if (i < len) {
            acc = qmul(sdot[i][threadIdx.x], acc);
            out[(size_t)(t0 + i + 1) * NS + n] = acc;
        }
    }
}

extern "C" void kernel_launch(void* const* d_in, const int* in_sizes, int n_in,
                              void* d_out, int out_size)
{
    const float4* q     = (const float4*)d_in[0];
    const float4* noise = (const float4*)d_in[1];
    float4* out         = (float4*)d_out;

    int quats0 = in_sizes[0] / 4;          // TS*NS
    int quats1 = in_sizes[1] / 4;          // (TS-1)*NS
    int NS = quats0 - quats1;
    int TS = quats0 / NS;
    int T  = TS - 1;
    int nch = (T + CHUNK - 1) / CHUNK;     // chunks (<= NCH_MAX)
    int CB  = (NS + BLK - 1) / BLK;        // column-blocks

    init_kernel<<<32, 256>>>();
    scan_kernel<<<nch * CB, BLK>>>(q, noise, out, NS, T, CB);
}

// round 9
// speedup vs baseline: 1.3274x; 1.0662x over previous
#include <cuda_runtime.h>

// PoseNoiseTransform single-pass decoupled-lookback quaternion scan.
// q_dot staged in SMEM (inputs read from DRAM exactly once); lookback is
// fully per-thread (per-column flags, acquire/release), no block syncs.
//
//   q:     [TS, NS, 4] f32 unit quaternions (w,x,y,z)
//   noise: [TS-1, NS, 4] f32 uniform [0,1)
//   out:   [TS, NS, 4] f32
//
// out[0]   = q[0]
// q_dot[t] = (q[t+1] * conj(q[t])) * normalize((noise[t]-0.5)*[1,.05,.05,.05])
// out[i+1] = q_dot[i] * ... * q_dot[0] * q[0]

#define BLK 256
#define CHUNK 11          // SMEM = 256*11*16 = 45056 B (< 48 KB static limit)
#define NCH_MAX 192
#define NS_MAX 8192

// Scratch (device globals; no allocation allowed anywhere).
__device__ float4 g_agg[NCH_MAX * NS_MAX];   // per-chunk aggregate, per column
__device__ float4 g_inc[NCH_MAX * NS_MAX];   // per-chunk inclusive, per column
__device__ int    g_flag[NCH_MAX * NS_MAX];  // per-column: 0=none 1=agg 2=inclusive
__device__ unsigned int g_vid;

// Quaternion in float4: .x=w .y=x .z=y .w=z ; returns a*b (Hamilton)
__device__ __forceinline__ float4 qmul(float4 a, float4 b) {
    float aw = a.x, ax = a.y, ay = a.z, az = a.w;
    float bw = b.x, bx = b.y, by = b.z, bz = b.w;
    return make_float4(
        aw * bw - ax * bx - ay * by - az * bz,
        aw * bx + ax * bw + ay * bz - az * by,
        aw * by - ax * bz + ay * bw + az * bx,
        aw * bz + ax * by - ay * bx + az * bw);
}

__device__ __forceinline__ float4 qdot_step(float4 qnext, float4 qprev, float4 nz) {
    // rel = qnext * conj(qprev), conj signs folded
    float aw = qnext.x, ax = qnext.y, ay = qnext.z, az = qnext.w;
    float bw = qprev.x, bx = -qprev.y, by = -qprev.z, bz = -qprev.w;
    float4 rel = make_float4(
        aw * bw - ax * bx - ay * by - az * bz,
        aw * bx + ax * bw + ay * bz - az * by,
        aw * by - ax * bz + ay * bw + az * bx,
        aw * bz + ax * by - ay * bx + az * bw);

    // q_samp = normalize((nz - 0.5) * [1, .05, .05, .05])
    float sw = nz.x - 0.5f;
    float sx = (nz.y - 0.5f) * 0.05f;
    float sy = (nz.z - 0.5f) * 0.05f;
    float sz = (nz.w - 0.5f) * 0.05f;
    float d = sw * sw + sx * sx + sy * sy + sz * sz;
    float r = rsqrtf(d);
    r = r * (1.5f - 0.5f * d * r * r);   // Newton step -> full fp32 accuracy
    float4 samp = make_float4(sw * r, sx * r, sy * r, sz * r);

    return qmul(rel, samp);
}

__device__ __forceinline__ int ld_acquire(const int* p) {
    int v;
    asm volatile("ld.acquire.gpu.global.b32 %0, [%1];" : "=r"(v) : "l"(p) : "memory");
    return v;
}
__device__ __forceinline__ void st_release(int* p, int v) {
    asm volatile("st.release.gpu.global.b32 [%0], %1;" :: "l"(p), "r"(v) : "memory");
}

__global__ void init_kernel() {
    int i = blockIdx.x * blockDim.x + threadIdx.x;
    int total = NCH_MAX * NS_MAX;
    for (int k = i; k < total; k += gridDim.x * blockDim.x) g_flag[k] = 0;
    if (i == 0) g_vid = 0u;
}

__global__ void __launch_bounds__(BLK) scan_kernel(
    const float4* __restrict__ q, const float4* __restrict__ noise,
    float4* __restrict__ out, int NS, int T, int CB)
{
    __shared__ float4 sdot[CHUNK][BLK];   // staged q_dot (each thread uses only its own column)
    __shared__ unsigned int s_vid;

    // Dynamic block id: scheduling order == chunk order -> lookback safe.
    if (threadIdx.x == 0) s_vid = atomicAdd(&g_vid, 1u);
    __syncthreads();
    unsigned int vid = s_vid;
    int c  = (int)(vid / (unsigned)CB);
    int cb = (int)(vid % (unsigned)CB);
    int n  = cb * BLK + threadIdx.x;
    if (n >= NS) return;                  // no cross-thread deps -> safe to exit

    int t0 = c * CHUNK;
    int t1 = min(T, t0 + CHUNK);
    int len = t1 - t0;                    // 1..CHUNK

    // ---- Walk 1: compute q_dot -> SMEM (own column), accumulate aggregate A ----
    float4 A = make_float4(1.f, 0.f, 0.f, 0.f);
    {
        float4 qprev = q[(size_t)t0 * NS + n];
        #pragma unroll
        for (int i = 0; i < CHUNK; ++i) {
            if (i < len) {
                int t = t0 + i;
                float4 qn = q[(size_t)(t + 1) * NS + n];
                float4 nz = noise[(size_t)t * NS + n];
                float4 qd = qdot_step(qn, qprev, nz);
                sdot[i][threadIdx.x] = qd;
                A = qmul(qd, A);
                qprev = qn;
            }
        }
    }

    // ---- Per-thread decoupled lookback (per-column flags) ----
    float4 S = make_float4(1.f, 0.f, 0.f, 0.f);  // exclusive prefix P_{c-1}
    if (c > 0) {
        g_agg[c * NS + n] = A;
        st_release(&g_flag[c * NS + n], 1);      // release orders payload

        int p = c - 1;
        while (true) {
            int s;
            int backoff = 16;
            while ((s = ld_acquire(&g_flag[p * NS + n])) == 0) {
                __nanosleep(backoff);
                if (backoff < 256) backoff += backoff;
            }
            if (s >= 2) { S = qmul(S, g_inc[p * NS + n]); break; }
            S = qmul(S, g_agg[p * NS + n]);
            if (--p < 0) break;
        }
    }

    // ---- Publish inclusive P_c = A * P_{c-1} ----
    float4 P = qmul(A, S);
    g_inc[c * NS + n] = P;
    st_release(&g_flag[c * NS + n], 2);

    // ---- Walk 2: replay q_dot from SMEM (own column), write outputs ----
    float4 q0 = q[n];
    if (c == 0) out[n] = q0;              // out[0] = q[0]
    float4 acc = qmul(S, q0);             // carry = P_{c-1} * q[0]
    #pragma unroll
    for (int i = 0; i < CHUNK; ++i) {
        if (i < len) {
            acc = qmul(sdot[i][threadIdx.x], acc);
            out[(size_t)(t0 + i + 1) * NS + n] = acc;
        }
    }
}

extern "C" void kernel_launch(void* const* d_in, const int* in_sizes, int n_in,
                              void* d_out, int out_size)
{
    const float4* q     = (const float4*)d_in[0];
    const float4* noise = (const float4*)d_in[1];
    float4* out         = (float4*)d_out;

    int quats0 = in_sizes[0] / 4;          // TS*NS
    int quats1 = in_sizes[1] / 4;          // (TS-1)*NS
    int NS = quats0 - quats1;
    int TS = quats0 / NS;
    int T  = TS - 1;
    int nch = (T + CHUNK - 1) / CHUNK;     // chunks (<= NCH_MAX)
    int CB  = (NS + BLK - 1) / BLK;        // column-blocks

    init_kernel<<<512, 256>>>();
    scan_kernel<<<nch * CB, BLK>>>(q, noise, out, NS, T, CB);
}